// round 14
// baseline (speedup 1.0000x reference)
#include <cuda_runtime.h>
#include <cuda_fp16.h>
#include <math.h>
#include <stdint.h>

#define NL 4
#define NB 32
#define NH 512
#define NV 32000
#define NTT 51
#define NDIAG (NTT + NL - 1)

typedef unsigned long long u64;

// ================= persistent device scratch =================
__device__ u64 g_x[2][NL][16][512];      // layer-input pairs (l>=1), ping-pong by t parity
__device__ u64 g_hb[2][NL][16][512];     // clamped hidden pairs, ping-pong by t parity
__device__ u64 g_c2[NL][16][512];        // clamped cell pairs
__device__ u64 g_emb2[NTT][16][512];     // pre-gathered embedding pairs per timestep

// fp16 operands for the projection (single pass); pad rows 1632..1663 stay 0
__device__ __half g_Hs[1664 * 512];
__device__ __half g_Ws[NV * 512];

// ================= helpers =================
__device__ __forceinline__ u64 pk2(float lo, float hi) {
    u64 r;
    asm("mov.b64 %0, {%1, %2};" : "=l"(r) : "r"(__float_as_uint(lo)), "r"(__float_as_uint(hi)));
    return r;
}
__device__ __forceinline__ void upk2(u64 v, float &lo, float &hi) {
    unsigned a, b;
    asm("mov.b64 {%0, %1}, %2;" : "=r"(a), "=r"(b) : "l"(v));
    lo = __uint_as_float(a); hi = __uint_as_float(b);
}
__device__ __forceinline__ u64 ffma2(u64 a, u64 b, u64 c) {
    u64 d;
    asm("fma.rn.f32x2 %0, %1, %2, %3;" : "=l"(d) : "l"(a), "l"(b), "l"(c));
    return d;
}
__device__ __forceinline__ u64 fadd2(u64 a, u64 b) {
    u64 d;
    asm("add.rn.f32x2 %0, %1, %2;" : "=l"(d) : "l"(a), "l"(b));
    return d;
}
__device__ __forceinline__ float sigmoidf_(float x) { return 1.0f / (1.0f + expf(-x)); }
__device__ __forceinline__ float clip50(float x) { return fminf(fmaxf(x, -50.0f), 50.0f); }

__device__ __forceinline__ uint32_t s2u(const void* p) {
    return (uint32_t)__cvta_generic_to_shared(p);
}
__device__ __forceinline__ void cpasync16(uint32_t dst, const void* src) {
    asm volatile("cp.async.cg.shared.global [%0], [%1], 16;" :: "r"(dst), "l"(src));
}
__device__ __forceinline__ void cp_commit() { asm volatile("cp.async.commit_group;" ::: "memory"); }
__device__ __forceinline__ void cp_wait1() { asm volatile("cp.async.wait_group 1;" ::: "memory"); }

#define LDMX4(r0, r1, r2, r3, a) \
    asm volatile("ldmatrix.sync.aligned.m8n8.x4.shared.b16 {%0,%1,%2,%3}, [%4];" \
                 : "=r"(r0), "=r"(r1), "=r"(r2), "=r"(r3) : "r"(a))

__device__ __forceinline__ void mma16816(float* d, const uint32_t* a, const uint32_t* b) {
    asm volatile("mma.sync.aligned.m16n8k16.row.col.f32.f16.f16.f32 "
                 "{%0,%1,%2,%3}, {%4,%5,%6,%7}, {%8,%9}, {%0,%1,%2,%3};"
                 : "+f"(d[0]), "+f"(d[1]), "+f"(d[2]), "+f"(d[3])
                 : "r"(a[0]), "r"(a[1]), "r"(a[2]), "r"(a[3]), "r"(b[0]), "r"(b[1]));
}

// ================= init kernels =================
__global__ void init_pair(const float* __restrict__ dh, const float* __restrict__ dc) {
    int idx = blockIdx.x * blockDim.x + threadIdx.x;   // 32768
    int l = idx >> 13, rem = idx & 8191, b2 = rem >> 9, j = rem & 511;
    int b0 = 2 * b2, b1 = b0 + 1;
    g_hb[0][l][b2][j] = pk2(dh[(l * 32 + b0) * 512 + j], dh[(l * 32 + b1) * 512 + j]);
    g_c2[l][b2][j]    = pk2(dc[(l * 32 + b0) * 512 + j], dc[(l * 32 + b1) * 512 + j]);
}

__global__ void init_emb(const float* __restrict__ emb, const int* __restrict__ target) {
    int idx = blockIdx.x * blockDim.x + threadIdx.x;   // 51*8192
    if (idx >= NTT * 8192) return;
    int t = idx >> 13, rem = idx & 8191, b2 = rem >> 9, k = rem & 511;
    int b0 = 2 * b2, b1 = b0 + 1;
    int t0 = (t == 0) ? 0 : target[b0 * NTT + t - 1];
    int t1 = (t == 0) ? 0 : target[b1 * NTT + t - 1];
    g_emb2[t][b2][k] = pk2(emb[t0 * 512 + k], emb[t1 * 512 + k]);
}

// round W_out to fp16 once
__global__ void conv_w(const float* __restrict__ W) {
    int idx = blockIdx.x * blockDim.x + threadIdx.x;   // 32000*64
    if (idx >= NV * 64) return;
    size_t base = (size_t)idx * 8;
    const float4* s = (const float4*)(W + base);
    float4 a = s[0], b = s[1];
    float v[8] = {a.x, a.y, a.z, a.w, b.x, b.y, b.z, b.w};
    __align__(16) __half h[8];
    #pragma unroll
    for (int i = 0; i < 8; i++) h[i] = __float2half_rn(v[i]);
    *(uint4*)&g_Ws[base] = *(const uint4*)h;
}

// ================= wavefront LSTM (R8/R13-proven configuration) =================
__global__ __launch_bounds__(256, 2) void lstm_diag(
    int d,
    const float* __restrict__ Wih, const float* __restrict__ Whh,
    const float* __restrict__ bih, const float* __restrict__ bhh)
{
    __shared__ u64 gates2[2 * 4 * 4 * 8];   // [khalf][gate][r][b2l] = 2KB

    const int lmin = (d > NTT - 1) ? d - (NTT - 1) : 0;
    const int within = blockIdx.x & 255;
    const int l = lmin + (blockIdx.x >> 8);
    const int t = d - l;
    const int par = t & 1;
    const int bhalf = within >> 7;
    const int j0 = (within & 127) * 4;
    const int tid = threadIdx.x, lane = tid & 31, wid = tid >> 5;

    const int khalf = wid & 1;
    const int gate  = (wid >> 1) & 3;

    const u64* xsrc = ((l == 0) ? &g_emb2[t][0][0] : &g_x[par][l][0][0]) + bhalf * 4096;
    const u64* hsrc = &g_hb[par][l][0][0] + bhalf * 4096;
    const u64* src  = (khalf ? hsrc : xsrc) + lane;

    const float* wp = (khalf ? Whh : Wih)
        + ((size_t)(l * 2048 + gate * 512 + j0)) * 512 + lane;

    // deep prefetch: 4 k-chunks of weights + 1 k-chunk of activations
    float wc[4][4];
    #pragma unroll
    for (int p = 0; p < 4; p++)
        #pragma unroll
        for (int r = 0; r < 4; r++) wc[p][r] = wp[r * 512 + p * 32];

    u64 xv[8];
    #pragma unroll
    for (int b = 0; b < 8; b++) xv[b] = src[b * 512];

    u64 acc[4][8];
    #pragma unroll
    for (int r = 0; r < 4; r++)
        #pragma unroll
        for (int b = 0; b < 8; b++) acc[r][b] = 0ULL;

    #pragma unroll
    for (int kc = 0; kc < 16; kc++) {
        const int sl = kc & 3;
        u64 aa[4];
        #pragma unroll
        for (int r = 0; r < 4; r++) aa[r] = pk2(wc[sl][r], wc[sl][r]);
        if (kc < 12) {
            #pragma unroll
            for (int r = 0; r < 4; r++) wc[sl][r] = wp[r * 512 + (kc + 4) * 32];
        }
        u64 xn[8];
        if (kc < 15) {
            #pragma unroll
            for (int b = 0; b < 8; b++) xn[b] = src[b * 512 + (kc + 1) * 32];
        }
        #pragma unroll
        for (int b = 0; b < 8; b++) {
            #pragma unroll
            for (int r = 0; r < 4; r++) acc[r][b] = ffma2(aa[r], xv[b], acc[r][b]);
        }
        if (kc < 15) {
            #pragma unroll
            for (int b = 0; b < 8; b++) xv[b] = xn[b];
        }
    }

    #pragma unroll
    for (int off = 16; off > 0; off >>= 1) {
        #pragma unroll
        for (int r = 0; r < 4; r++)
            #pragma unroll
            for (int b = 0; b < 8; b++)
                acc[r][b] = fadd2(acc[r][b], __shfl_xor_sync(0xffffffffu, acc[r][b], off));
    }
    if (lane == 0) {
        #pragma unroll
        for (int r = 0; r < 4; r++)
            #pragma unroll
            for (int b = 0; b < 8; b++)
                gates2[(((khalf * 4 + gate) * 4) + r) * 8 + b] = acc[r][b];
    }
    __syncthreads();

    // ---- pointwise epilogue: 4 j x 8 b2 = 32 threads ----
    if (tid < 32) {
        int jl = tid >> 3, b2l = tid & 7;
        int b2 = bhalf * 8 + b2l;
        int j = j0 + jl;
        float gv0[4], gv1[4];
        #pragma unroll
        for (int g = 0; g < 4; g++) {
            u64 s = fadd2(gates2[((0 * 4 + g) * 4 + jl) * 8 + b2l],
                          gates2[((1 * 4 + g) * 4 + jl) * 8 + b2l]);
            float lo, hi; upk2(s, lo, hi);
            float bb = bih[l * 2048 + g * 512 + j] + bhh[l * 2048 + g * 512 + j];
            gv0[g] = lo + bb; gv1[g] = hi + bb;
        }
        float c0, c1; upk2(g_c2[l][b2][j], c0, c1);

        float i0 = sigmoidf_(gv0[0]), f0 = sigmoidf_(gv0[1]);
        float gg0 = tanhf(gv0[2]),   o0 = sigmoidf_(gv0[3]);
        float cn0 = f0 * c0 + i0 * gg0;
        float h0 = o0 * tanhf(cn0);

        float i1 = sigmoidf_(gv1[0]), f1 = sigmoidf_(gv1[1]);
        float gg1 = tanhf(gv1[2]),   o1 = sigmoidf_(gv1[3]);
        float cn1 = f1 * c1 + i1 * gg1;
        float h1 = o1 * tanhf(cn1);

        if (l < 3) {
            g_x[par][l + 1][b2][j] = pk2(h0, h1);
        } else {
            int b0 = 2 * b2;                         // fp16 operand for proj, direct
            g_Hs[((size_t)t * 32 + b0) * 512 + j] = __float2half_rn(h0);
            g_Hs[((size_t)t * 32 + b0 + 1) * 512 + j] = __float2half_rn(h1);
        }
        g_hb[par ^ 1][l][b2][j] = pk2(clip50(h0), clip50(h1));
        g_c2[l][b2][j] = pk2(clip50(cn0), clip50(cn1));
    }
}

// ================= mma.sync fp16 projection (single pass, chunked M) =================
// One M-tile (mt) of C[1664,32000] = A @ W^T, K=512 (8 chunks of 64).
// BM=BN=128, BK=64 (128B rows, XOR swizzle), 8 warps (4m x 2n), warp tile 32x64.
__global__ __launch_bounds__(256) void proj_mma(
    int mt, const float* __restrict__ bout, float* __restrict__ out)
{
    extern __shared__ __align__(16) unsigned char ps[];
    const uint32_t sb = s2u(ps);
    const int tid = threadIdx.x, lane = tid & 31, wid = tid >> 5;
    const int wm = wid & 3, wn = wid >> 2;
    const int bm = mt * 128, bn = blockIdx.x * 128;

    const uint32_t Ab[2] = {sb, sb + 16384};
    const uint32_t Bb[2] = {sb + 32768, sb + 49152};

    float acc[2][8][4];
    #pragma unroll
    for (int f = 0; f < 2; f++)
        #pragma unroll
        for (int p = 0; p < 8; p++)
            #pragma unroll
            for (int q = 0; q < 4; q++) acc[f][p][q] = 0.0f;

    const int sr = tid >> 3, su = tid & 7;

    // prologue: chunk 0
    #pragma unroll
    for (int i = 0; i < 4; i++) {
        int r = sr + i * 32;
        cpasync16(Ab[0] + r * 128 + ((su ^ (r & 7)) << 4),
                  g_Hs + (size_t)(bm + r) * 512 + su * 8);
        cpasync16(Bb[0] + r * 128 + ((su ^ (r & 7)) << 4),
                  g_Ws + (size_t)(bn + r) * 512 + su * 8);
    }
    cp_commit();

    for (int c = 0; c < 8; c++) {
        if (c + 1 < 8) {
            int k0 = (c + 1) * 64;
            uint32_t da = Ab[(c + 1) & 1], db = Bb[(c + 1) & 1];
            #pragma unroll
            for (int i = 0; i < 4; i++) {
                int r = sr + i * 32;
                cpasync16(da + r * 128 + ((su ^ (r & 7)) << 4),
                          g_Hs + (size_t)(bm + r) * 512 + k0 + su * 8);
                cpasync16(db + r * 128 + ((su ^ (r & 7)) << 4),
                          g_Ws + (size_t)(bn + r) * 512 + k0 + su * 8);
            }
        }
        cp_commit();
        cp_wait1();
        __syncthreads();

        const uint32_t Abase = Ab[c & 1], Bbase = Bb[c & 1];
        const int jA = lane >> 3;
        #pragma unroll
        for (int q = 0; q < 4; q++) {
            uint32_t a[2][4];
            #pragma unroll
            for (int f = 0; f < 2; f++) {
                int r = wm * 32 + f * 16 + (lane & 7) + ((jA & 1) << 3);
                int uu = 2 * q + (jA >> 1);
                uint32_t ad = Abase + r * 128 + ((uu ^ (r & 7)) << 4);
                LDMX4(a[f][0], a[f][1], a[f][2], a[f][3], ad);
            }
            uint32_t b[8][2];
            #pragma unroll
            for (int fp = 0; fp < 4; fp++) {
                int r = wn * 64 + fp * 16 + (lane & 7) + ((jA >> 1) << 3);
                int uu = 2 * q + (jA & 1);
                uint32_t bd = Bbase + r * 128 + ((uu ^ (r & 7)) << 4);
                LDMX4(b[2 * fp][0], b[2 * fp][1], b[2 * fp + 1][0], b[2 * fp + 1][1], bd);
            }
            #pragma unroll
            for (int f = 0; f < 2; f++)
                #pragma unroll
                for (int p = 0; p < 8; p++)
                    mma16816(acc[f][p], a[f], b[p]);
        }
        __syncthreads();
    }

    // epilogue: C[m][n] + bias, remap m=(t*32+b) -> out[b][t][:]
    #pragma unroll
    for (int f = 0; f < 2; f++) {
        int m0 = bm + wm * 32 + f * 16 + (lane >> 2);
        #pragma unroll
        for (int p = 0; p < 8; p++) {
            int n = bn + wn * 64 + p * 8 + 2 * (lane & 3);
            float2 bo = *(const float2*)&bout[n];
            int m = m0;
            if (m < 1632) {
                int tt = m >> 5, b = m & 31;
                float2 r0 = make_float2(acc[f][p][0] + bo.x, acc[f][p][1] + bo.y);
                *(float2*)&out[(size_t)b * NTT * NV + (size_t)tt * NV + n] = r0;
            }
            m = m0 + 8;
            if (m < 1632) {
                int tt = m >> 5, b = m & 31;
                float2 r1 = make_float2(acc[f][p][2] + bo.x, acc[f][p][3] + bo.y);
                *(float2*)&out[(size_t)b * NTT * NV + (size_t)tt * NV + n] = r1;
            }
        }
    }
}

// ================= final hidden state tail =================
__global__ void write_hfin(float* __restrict__ out) {
    int idx = blockIdx.x * blockDim.x + threadIdx.x;   // 65536
    int l = idx >> 14, b = (idx >> 9) & 31, j = idx & 511;
    float lo, hi; upk2(g_hb[1][l][b >> 1][j], lo, hi);
    out[(size_t)NB * NTT * NV + idx] = (b & 1) ? hi : lo;
}

// ================= launcher with fork/join side stream =================
extern "C" void kernel_launch(void* const* d_in, const int* in_sizes, int n_in,
                              void* d_out, int out_size)
{
    (void)in_sizes; (void)n_in; (void)out_size;
    const float* dh   = (const float*)d_in[1];
    const float* dc   = (const float*)d_in[2];
    const int*   tgt  = (const int*)  d_in[3];
    const float* emb  = (const float*)d_in[4];
    const float* Wih  = (const float*)d_in[5];
    const float* Whh  = (const float*)d_in[6];
    const float* bih  = (const float*)d_in[7];
    const float* bhh  = (const float*)d_in[8];
    const float* Wout = (const float*)d_in[9];
    const float* bout = (const float*)d_in[10];
    float* out = (float*)d_out;

    const int SMEM_PROJ = 65536;
    cudaFuncSetAttribute(proj_mma, cudaFuncAttributeMaxDynamicSharedMemorySize, SMEM_PROJ);

    // one-time resource creation (streams/events only; no device memory, work
    // per call is identical every time)
    static cudaStream_t s2 = nullptr;
    static cudaEvent_t ev_start = nullptr, ev_join = nullptr, evF[13];
    static bool have_s2 = false;
    if (!s2 && !have_s2) {
        bool ok = (cudaStreamCreateWithFlags(&s2, cudaStreamNonBlocking) == cudaSuccess);
        ok = ok && (cudaEventCreateWithFlags(&ev_start, cudaEventDisableTiming) == cudaSuccess);
        ok = ok && (cudaEventCreateWithFlags(&ev_join, cudaEventDisableTiming) == cudaSuccess);
        for (int i = 0; i < 13 && ok; i++)
            ok = (cudaEventCreateWithFlags(&evF[i], cudaEventDisableTiming) == cudaSuccess);
        have_s2 = ok;
        if (!ok) s2 = nullptr;
    }

    init_pair<<<128, 256>>>(dh, dc);
    init_emb<<<1632, 256>>>(emb, tgt);

    if (have_s2) {
        cudaEventRecord(ev_start, 0);

        // main stream: LSTM wavefront, recording readiness events for M-tiles
        for (int d = 0; d < NDIAG; d++) {
            int lmin = (d > NTT - 1) ? d - (NTT - 1) : 0;
            int lmax = (d < NL - 1) ? d : NL - 1;
            int ns = lmax - lmin + 1;
            lstm_diag<<<256 * ns, 256>>>(d, Wih, Whh, bih, bhh);
            if (d >= 6 && d <= 50 && ((d - 6) & 3) == 0)
                cudaEventRecord(evF[(d - 6) >> 2], 0);   // tiles 0..11
        }
        cudaEventRecord(evF[12], 0);                      // tile 12: after d=53
        write_hfin<<<256, 256>>>(out);

        // side stream: conv_w, then projection M-tiles as they become ready
        cudaStreamWaitEvent(s2, ev_start, 0);
        conv_w<<<8000, 256, 0, s2>>>(Wout);
        for (int i = 0; i < 13; i++) {
            cudaStreamWaitEvent(s2, evF[i], 0);
            proj_mma<<<dim3(250, 1), 256, SMEM_PROJ, s2>>>(i, bout, out);
        }
        cudaEventRecord(ev_join, s2);
        cudaStreamWaitEvent((cudaStream_t)0, ev_join, 0);
    } else {
        // fallback: fully serial on the default stream (R13 behavior)
        conv_w<<<8000, 256>>>(Wout);
        for (int d = 0; d < NDIAG; d++) {
            int lmin = (d > NTT - 1) ? d - (NTT - 1) : 0;
            int lmax = (d < NL - 1) ? d : NL - 1;
            int ns = lmax - lmin + 1;
            lstm_diag<<<256 * ns, 256>>>(d, Wih, Whh, bih, bhh);
        }
        for (int i = 0; i < 13; i++)
            proj_mma<<<dim3(250, 1), 256, SMEM_PROJ>>>(i, bout, out);
        write_hfin<<<256, 256>>>(out);
    }
}

// round 15
// speedup vs baseline: 1.0435x; 1.0435x over previous
#include <cuda_runtime.h>
#include <cuda_fp16.h>
#include <math.h>
#include <stdint.h>

#define NL 4
#define NB 32
#define NH 512
#define NV 32000
#define NTT 51
#define NDIAG (NTT + NL - 1)

typedef unsigned long long u64;

// ================= persistent device scratch =================
__device__ u64 g_x[2][NL][16][512];      // layer-input pairs (l>=1), ping-pong by t parity
__device__ u64 g_hb[2][NL][16][512];     // clamped hidden pairs, ping-pong by t parity
__device__ u64 g_c2[NL][16][512];        // clamped cell pairs
__device__ u64 g_emb2[NTT][16][512];     // pre-gathered embedding pairs per timestep

// fp16 operands for the projection (single pass); pad rows 1632..1663 stay 0
__device__ __half g_Hs[1664 * 512];
__device__ __half g_Ws[NV * 512];

// ================= helpers =================
__device__ __forceinline__ u64 pk2(float lo, float hi) {
    u64 r;
    asm("mov.b64 %0, {%1, %2};" : "=l"(r) : "r"(__float_as_uint(lo)), "r"(__float_as_uint(hi)));
    return r;
}
__device__ __forceinline__ void upk2(u64 v, float &lo, float &hi) {
    unsigned a, b;
    asm("mov.b64 {%0, %1}, %2;" : "=r"(a), "=r"(b) : "l"(v));
    lo = __uint_as_float(a); hi = __uint_as_float(b);
}
__device__ __forceinline__ u64 ffma2(u64 a, u64 b, u64 c) {
    u64 d;
    asm("fma.rn.f32x2 %0, %1, %2, %3;" : "=l"(d) : "l"(a), "l"(b), "l"(c));
    return d;
}
__device__ __forceinline__ u64 fadd2(u64 a, u64 b) {
    u64 d;
    asm("add.rn.f32x2 %0, %1, %2;" : "=l"(d) : "l"(a), "l"(b));
    return d;
}
__device__ __forceinline__ float sigmoidf_(float x) { return 1.0f / (1.0f + expf(-x)); }
__device__ __forceinline__ float clip50(float x) { return fminf(fmaxf(x, -50.0f), 50.0f); }

__device__ __forceinline__ uint32_t s2u(const void* p) {
    return (uint32_t)__cvta_generic_to_shared(p);
}
__device__ __forceinline__ void cpasync16(uint32_t dst, const void* src) {
    asm volatile("cp.async.cg.shared.global [%0], [%1], 16;" :: "r"(dst), "l"(src));
}
__device__ __forceinline__ void cp_commit() { asm volatile("cp.async.commit_group;" ::: "memory"); }
__device__ __forceinline__ void cp_wait1() { asm volatile("cp.async.wait_group 1;" ::: "memory"); }

#define LDMX4(r0, r1, r2, r3, a) \
    asm volatile("ldmatrix.sync.aligned.m8n8.x4.shared.b16 {%0,%1,%2,%3}, [%4];" \
                 : "=r"(r0), "=r"(r1), "=r"(r2), "=r"(r3) : "r"(a))

__device__ __forceinline__ void mma16816(float* d, const uint32_t* a, const uint32_t* b) {
    asm volatile("mma.sync.aligned.m16n8k16.row.col.f32.f16.f16.f32 "
                 "{%0,%1,%2,%3}, {%4,%5,%6,%7}, {%8,%9}, {%0,%1,%2,%3};"
                 : "+f"(d[0]), "+f"(d[1]), "+f"(d[2]), "+f"(d[3])
                 : "r"(a[0]), "r"(a[1]), "r"(a[2]), "r"(a[3]), "r"(b[0]), "r"(b[1]));
}

// ================= init kernels =================
__global__ void init_pair(const float* __restrict__ dh, const float* __restrict__ dc) {
    int idx = blockIdx.x * blockDim.x + threadIdx.x;   // 32768
    int l = idx >> 13, rem = idx & 8191, b2 = rem >> 9, j = rem & 511;
    int b0 = 2 * b2, b1 = b0 + 1;
    g_hb[0][l][b2][j] = pk2(dh[(l * 32 + b0) * 512 + j], dh[(l * 32 + b1) * 512 + j]);
    g_c2[l][b2][j]    = pk2(dc[(l * 32 + b0) * 512 + j], dc[(l * 32 + b1) * 512 + j]);
}

__global__ void init_emb(const float* __restrict__ emb, const int* __restrict__ target) {
    int idx = blockIdx.x * blockDim.x + threadIdx.x;   // 51*8192
    if (idx >= NTT * 8192) return;
    int t = idx >> 13, rem = idx & 8191, b2 = rem >> 9, k = rem & 511;
    int b0 = 2 * b2, b1 = b0 + 1;
    int t0 = (t == 0) ? 0 : target[b0 * NTT + t - 1];
    int t1 = (t == 0) ? 0 : target[b1 * NTT + t - 1];
    g_emb2[t][b2][k] = pk2(emb[t0 * 512 + k], emb[t1 * 512 + k]);
}

// round W_out to fp16 once
__global__ void conv_w(const float* __restrict__ W) {
    int idx = blockIdx.x * blockDim.x + threadIdx.x;   // 32000*64
    if (idx >= NV * 64) return;
    size_t base = (size_t)idx * 8;
    const float4* s = (const float4*)(W + base);
    float4 a = s[0], b = s[1];
    float v[8] = {a.x, a.y, a.z, a.w, b.x, b.y, b.z, b.w};
    __align__(16) __half h[8];
    #pragma unroll
    for (int i = 0; i < 8; i++) h[i] = __float2half_rn(v[i]);
    *(uint4*)&g_Ws[base] = *(const uint4*)h;
}

// ================= wavefront LSTM (R13-proven configuration, unchanged) =================
__global__ __launch_bounds__(256, 2) void lstm_diag(
    int d,
    const float* __restrict__ Wih, const float* __restrict__ Whh,
    const float* __restrict__ bih, const float* __restrict__ bhh)
{
    __shared__ u64 gates2[2 * 4 * 4 * 8];   // [khalf][gate][r][b2l] = 2KB

    const int lmin = (d > NTT - 1) ? d - (NTT - 1) : 0;
    const int within = blockIdx.x & 255;
    const int l = lmin + (blockIdx.x >> 8);
    const int t = d - l;
    const int par = t & 1;
    const int bhalf = within >> 7;
    const int j0 = (within & 127) * 4;
    const int tid = threadIdx.x, lane = tid & 31, wid = tid >> 5;

    const int khalf = wid & 1;
    const int gate  = (wid >> 1) & 3;

    const u64* xsrc = ((l == 0) ? &g_emb2[t][0][0] : &g_x[par][l][0][0]) + bhalf * 4096;
    const u64* hsrc = &g_hb[par][l][0][0] + bhalf * 4096;
    const u64* src  = (khalf ? hsrc : xsrc) + lane;

    const float* wp = (khalf ? Whh : Wih)
        + ((size_t)(l * 2048 + gate * 512 + j0)) * 512 + lane;

    // deep prefetch: 4 k-chunks of weights + 1 k-chunk of activations
    float wc[4][4];
    #pragma unroll
    for (int p = 0; p < 4; p++)
        #pragma unroll
        for (int r = 0; r < 4; r++) wc[p][r] = wp[r * 512 + p * 32];

    u64 xv[8];
    #pragma unroll
    for (int b = 0; b < 8; b++) xv[b] = src[b * 512];

    u64 acc[4][8];
    #pragma unroll
    for (int r = 0; r < 4; r++)
        #pragma unroll
        for (int b = 0; b < 8; b++) acc[r][b] = 0ULL;

    #pragma unroll
    for (int kc = 0; kc < 16; kc++) {
        const int sl = kc & 3;
        u64 aa[4];
        #pragma unroll
        for (int r = 0; r < 4; r++) aa[r] = pk2(wc[sl][r], wc[sl][r]);
        if (kc < 12) {
            #pragma unroll
            for (int r = 0; r < 4; r++) wc[sl][r] = wp[r * 512 + (kc + 4) * 32];
        }
        u64 xn[8];
        if (kc < 15) {
            #pragma unroll
            for (int b = 0; b < 8; b++) xn[b] = src[b * 512 + (kc + 1) * 32];
        }
        #pragma unroll
        for (int b = 0; b < 8; b++) {
            #pragma unroll
            for (int r = 0; r < 4; r++) acc[r][b] = ffma2(aa[r], xv[b], acc[r][b]);
        }
        if (kc < 15) {
            #pragma unroll
            for (int b = 0; b < 8; b++) xv[b] = xn[b];
        }
    }

    #pragma unroll
    for (int off = 16; off > 0; off >>= 1) {
        #pragma unroll
        for (int r = 0; r < 4; r++)
            #pragma unroll
            for (int b = 0; b < 8; b++)
                acc[r][b] = fadd2(acc[r][b], __shfl_xor_sync(0xffffffffu, acc[r][b], off));
    }
    if (lane == 0) {
        #pragma unroll
        for (int r = 0; r < 4; r++)
            #pragma unroll
            for (int b = 0; b < 8; b++)
                gates2[(((khalf * 4 + gate) * 4) + r) * 8 + b] = acc[r][b];
    }
    __syncthreads();

    // ---- pointwise epilogue: 4 j x 8 b2 = 32 threads ----
    if (tid < 32) {
        int jl = tid >> 3, b2l = tid & 7;
        int b2 = bhalf * 8 + b2l;
        int j = j0 + jl;
        float gv0[4], gv1[4];
        #pragma unroll
        for (int g = 0; g < 4; g++) {
            u64 s = fadd2(gates2[((0 * 4 + g) * 4 + jl) * 8 + b2l],
                          gates2[((1 * 4 + g) * 4 + jl) * 8 + b2l]);
            float lo, hi; upk2(s, lo, hi);
            float bb = bih[l * 2048 + g * 512 + j] + bhh[l * 2048 + g * 512 + j];
            gv0[g] = lo + bb; gv1[g] = hi + bb;
        }
        float c0, c1; upk2(g_c2[l][b2][j], c0, c1);

        float i0 = sigmoidf_(gv0[0]), f0 = sigmoidf_(gv0[1]);
        float gg0 = tanhf(gv0[2]),   o0 = sigmoidf_(gv0[3]);
        float cn0 = f0 * c0 + i0 * gg0;
        float h0 = o0 * tanhf(cn0);

        float i1 = sigmoidf_(gv1[0]), f1 = sigmoidf_(gv1[1]);
        float gg1 = tanhf(gv1[2]),   o1 = sigmoidf_(gv1[3]);
        float cn1 = f1 * c1 + i1 * gg1;
        float h1 = o1 * tanhf(cn1);

        if (l < 3) {
            g_x[par][l + 1][b2][j] = pk2(h0, h1);
        } else {
            int b0 = 2 * b2;                         // fp16 operand for proj, direct
            g_Hs[((size_t)t * 32 + b0) * 512 + j] = __float2half_rn(h0);
            g_Hs[((size_t)t * 32 + b0 + 1) * 512 + j] = __float2half_rn(h1);
        }
        g_hb[par ^ 1][l][b2][j] = pk2(clip50(h0), clip50(h1));
        g_c2[l][b2][j] = pk2(clip50(cn0), clip50(cn1));
    }
}

// ================= mma.sync fp16 projection (single pass, chunked M) =================
__global__ __launch_bounds__(256) void proj_mma(
    int mt, const float* __restrict__ bout, float* __restrict__ out)
{
    extern __shared__ __align__(16) unsigned char ps[];
    const uint32_t sb = s2u(ps);
    const int tid = threadIdx.x, lane = tid & 31, wid = tid >> 5;
    const int wm = wid & 3, wn = wid >> 2;
    const int bm = mt * 128, bn = blockIdx.x * 128;

    const uint32_t Ab[2] = {sb, sb + 16384};
    const uint32_t Bb[2] = {sb + 32768, sb + 49152};

    float acc[2][8][4];
    #pragma unroll
    for (int f = 0; f < 2; f++)
        #pragma unroll
        for (int p = 0; p < 8; p++)
            #pragma unroll
            for (int q = 0; q < 4; q++) acc[f][p][q] = 0.0f;

    const int sr = tid >> 3, su = tid & 7;

    // prologue: chunk 0
    #pragma unroll
    for (int i = 0; i < 4; i++) {
        int r = sr + i * 32;
        cpasync16(Ab[0] + r * 128 + ((su ^ (r & 7)) << 4),
                  g_Hs + (size_t)(bm + r) * 512 + su * 8);
        cpasync16(Bb[0] + r * 128 + ((su ^ (r & 7)) << 4),
                  g_Ws + (size_t)(bn + r) * 512 + su * 8);
    }
    cp_commit();

    for (int c = 0; c < 8; c++) {
        if (c + 1 < 8) {
            int k0 = (c + 1) * 64;
            uint32_t da = Ab[(c + 1) & 1], db = Bb[(c + 1) & 1];
            #pragma unroll
            for (int i = 0; i < 4; i++) {
                int r = sr + i * 32;
                cpasync16(da + r * 128 + ((su ^ (r & 7)) << 4),
                          g_Hs + (size_t)(bm + r) * 512 + k0 + su * 8);
                cpasync16(db + r * 128 + ((su ^ (r & 7)) << 4),
                          g_Ws + (size_t)(bn + r) * 512 + k0 + su * 8);
            }
        }
        cp_commit();
        cp_wait1();
        __syncthreads();

        const uint32_t Abase = Ab[c & 1], Bbase = Bb[c & 1];
        const int jA = lane >> 3;
        #pragma unroll
        for (int q = 0; q < 4; q++) {
            uint32_t a[2][4];
            #pragma unroll
            for (int f = 0; f < 2; f++) {
                int r = wm * 32 + f * 16 + (lane & 7) + ((jA & 1) << 3);
                int uu = 2 * q + (jA >> 1);
                uint32_t ad = Abase + r * 128 + ((uu ^ (r & 7)) << 4);
                LDMX4(a[f][0], a[f][1], a[f][2], a[f][3], ad);
            }
            uint32_t b[8][2];
            #pragma unroll
            for (int fp = 0; fp < 4; fp++) {
                int r = wn * 64 + fp * 16 + (lane & 7) + ((jA >> 1) << 3);
                int uu = 2 * q + (jA & 1);
                uint32_t bd = Bbase + r * 128 + ((uu ^ (r & 7)) << 4);
                LDMX4(b[2 * fp][0], b[2 * fp][1], b[2 * fp + 1][0], b[2 * fp + 1][1], bd);
            }
            #pragma unroll
            for (int f = 0; f < 2; f++)
                #pragma unroll
                for (int p = 0; p < 8; p++)
                    mma16816(acc[f][p], a[f], b[p]);
        }
        __syncthreads();
    }

    // epilogue: C[m][n] + bias, remap m=(t*32+b) -> out[b][t][:]
    #pragma unroll
    for (int f = 0; f < 2; f++) {
        int m0 = bm + wm * 32 + f * 16 + (lane >> 2);
        #pragma unroll
        for (int p = 0; p < 8; p++) {
            int n = bn + wn * 64 + p * 8 + 2 * (lane & 3);
            float2 bo = *(const float2*)&bout[n];
            int m = m0;
            if (m < 1632) {
                int tt = m >> 5, b = m & 31;
                float2 r0 = make_float2(acc[f][p][0] + bo.x, acc[f][p][1] + bo.y);
                *(float2*)&out[(size_t)b * NTT * NV + (size_t)tt * NV + n] = r0;
            }
            m = m0 + 8;
            if (m < 1632) {
                int tt = m >> 5, b = m & 31;
                float2 r1 = make_float2(acc[f][p][2] + bo.x, acc[f][p][3] + bo.y);
                *(float2*)&out[(size_t)b * NTT * NV + (size_t)tt * NV + n] = r1;
            }
        }
    }
}

// ================= final hidden state tail =================
__global__ void write_hfin(float* __restrict__ out) {
    int idx = blockIdx.x * blockDim.x + threadIdx.x;   // 65536
    int l = idx >> 14, b = (idx >> 9) & 31, j = idx & 511;
    float lo, hi; upk2(g_hb[1][l][b >> 1][j], lo, hi);
    out[(size_t)NB * NTT * NV + idx] = (b & 1) ? hi : lo;
}

// ================= launcher: priority-asymmetric fork/join =================
extern "C" void kernel_launch(void* const* d_in, const int* in_sizes, int n_in,
                              void* d_out, int out_size)
{
    (void)in_sizes; (void)n_in; (void)out_size;
    const float* dh   = (const float*)d_in[1];
    const float* dc   = (const float*)d_in[2];
    const int*   tgt  = (const int*)  d_in[3];
    const float* emb  = (const float*)d_in[4];
    const float* Wih  = (const float*)d_in[5];
    const float* Whh  = (const float*)d_in[6];
    const float* bih  = (const float*)d_in[7];
    const float* bhh  = (const float*)d_in[8];
    const float* Wout = (const float*)d_in[9];
    const float* bout = (const float*)d_in[10];
    float* out = (float*)d_out;

    const int SMEM_PROJ = 65536;
    cudaFuncSetAttribute(proj_mma, cudaFuncAttributeMaxDynamicSharedMemorySize, SMEM_PROJ);

    // one-time resource creation (streams/events only; same work every call)
    static cudaStream_t s_hi = nullptr, s_lo = nullptr;
    static cudaEvent_t ev_start = nullptr, ev_hi_done = nullptr, ev_lo_done = nullptr, evF[13];
    static bool have_streams = false, tried = false;
    if (!tried) {
        tried = true;
        int prLeast = 0, prGreatest = 0;
        bool ok = (cudaDeviceGetStreamPriorityRange(&prLeast, &prGreatest) == cudaSuccess);
        ok = ok && (cudaStreamCreateWithPriority(&s_hi, cudaStreamNonBlocking, prGreatest) == cudaSuccess);
        ok = ok && (cudaStreamCreateWithPriority(&s_lo, cudaStreamNonBlocking, prLeast) == cudaSuccess);
        ok = ok && (cudaEventCreateWithFlags(&ev_start, cudaEventDisableTiming) == cudaSuccess);
        ok = ok && (cudaEventCreateWithFlags(&ev_hi_done, cudaEventDisableTiming) == cudaSuccess);
        ok = ok && (cudaEventCreateWithFlags(&ev_lo_done, cudaEventDisableTiming) == cudaSuccess);
        for (int i = 0; i < 13 && ok; i++)
            ok = (cudaEventCreateWithFlags(&evF[i], cudaEventDisableTiming) == cudaSuccess);
        have_streams = ok;
    }

    if (have_streams) {
        // fork from the capture stream
        init_pair<<<128, 256>>>(dh, dc);
        init_emb<<<1632, 256>>>(emb, tgt);
        cudaEventRecord(ev_start, 0);
        cudaStreamWaitEvent(s_hi, ev_start, 0);
        cudaStreamWaitEvent(s_lo, ev_start, 0);

        // HIGH priority: the LSTM critical path
        for (int d = 0; d < NDIAG; d++) {
            int lmin = (d > NTT - 1) ? d - (NTT - 1) : 0;
            int lmax = (d < NL - 1) ? d : NL - 1;
            int ns = lmax - lmin + 1;
            lstm_diag<<<256 * ns, 256, 0, s_hi>>>(d, Wih, Whh, bih, bhh);
            if (d >= 6 && d <= 50 && ((d - 6) & 3) == 0)
                cudaEventRecord(evF[(d - 6) >> 2], s_hi);   // tiles 0..11 ready
        }
        cudaEventRecord(evF[12], s_hi);                      // tile 12: after d=53
        write_hfin<<<256, 256, 0, s_hi>>>(out);
        cudaEventRecord(ev_hi_done, s_hi);

        // LOW priority: conv_w then projection M-tiles (backfill wave tails)
        conv_w<<<8000, 256, 0, s_lo>>>(Wout);
        for (int i = 0; i < 13; i++) {
            cudaStreamWaitEvent(s_lo, evF[i], 0);
            proj_mma<<<dim3(250, 1), 256, SMEM_PROJ, s_lo>>>(i, bout, out);
        }
        cudaEventRecord(ev_lo_done, s_lo);

        // join back into the capture stream
        cudaStreamWaitEvent((cudaStream_t)0, ev_hi_done, 0);
        cudaStreamWaitEvent((cudaStream_t)0, ev_lo_done, 0);
    } else {
        // fallback: fully serial R13 behavior
        init_pair<<<128, 256>>>(dh, dc);
        init_emb<<<1632, 256>>>(emb, tgt);
        conv_w<<<8000, 256>>>(Wout);
        for (int d = 0; d < NDIAG; d++) {
            int lmin = (d > NTT - 1) ? d - (NTT - 1) : 0;
            int lmax = (d < NL - 1) ? d : NL - 1;
            int ns = lmax - lmin + 1;
            lstm_diag<<<256 * ns, 256>>>(d, Wih, Whh, bih, bhh);
        }
        for (int i = 0; i < 13; i++)
            proj_mma<<<dim3(250, 1), 256, SMEM_PROJ>>>(i, bout, out);
        write_hfin<<<256, 256>>>(out);
    }
}

// round 16
// speedup vs baseline: 1.0560x; 1.0120x over previous
#include <cuda_runtime.h>
#include <cuda_fp16.h>
#include <math.h>
#include <stdint.h>

#define NL 4
#define NB 32
#define NH 512
#define NV 32000
#define NTT 51
#define NDIAG (NTT + NL - 1)

// ================= persistent device scratch =================
// Activation buffers, fp16, cols = [x_hi(0:1024) | h_hi... ] layout:
//   k 0..511 = x_hi, 512..1023 = h_hi, 1024..1535 = x_lo, 1536..2047 = h_lo
__device__ __half g_A[2][NL][NB][2048];      // ping-pong by t parity
__device__ __half g_embA[NTT][NB][2048];     // x-cols only, per timestep (l=0)
__device__ __half g_Wcat[NL][2048][2048];    // reordered combined W: hi(0:1024)|lo(1024:2048)
__device__ float  g_c[NL][NB][NH];           // cell state fp32 (clamped)
__device__ float  g_hfin[NL][NB][NH];        // final clamped hidden (t=50)
__device__ __half g_Hs[1664 * 512];          // proj A operand (pad rows stay 0)
__device__ __half g_Ws[NV * 512];            // proj B operand

// ================= helpers =================
__device__ __forceinline__ float sigmoidf_(float x) { return 1.0f / (1.0f + expf(-x)); }
__device__ __forceinline__ float clip50(float x) { return fminf(fmaxf(x, -50.0f), 50.0f); }

__device__ __forceinline__ uint32_t s2u(const void* p) {
    return (uint32_t)__cvta_generic_to_shared(p);
}
__device__ __forceinline__ void cpasync16(uint32_t dst, const void* src) {
    asm volatile("cp.async.cg.shared.global [%0], [%1], 16;" :: "r"(dst), "l"(src));
}
__device__ __forceinline__ void cp_commit() { asm volatile("cp.async.commit_group;" ::: "memory"); }
__device__ __forceinline__ void cp_wait1() { asm volatile("cp.async.wait_group 1;" ::: "memory"); }

#define LDMX4(r0, r1, r2, r3, a) \
    asm volatile("ldmatrix.sync.aligned.m8n8.x4.shared.b16 {%0,%1,%2,%3}, [%4];" \
                 : "=r"(r0), "=r"(r1), "=r"(r2), "=r"(r3) : "r"(a))

__device__ __forceinline__ void mma16816(float* d, const uint32_t* a, const uint32_t* b) {
    asm volatile("mma.sync.aligned.m16n8k16.row.col.f32.f16.f16.f32 "
                 "{%0,%1,%2,%3}, {%4,%5,%6,%7}, {%8,%9}, {%0,%1,%2,%3};"
                 : "+f"(d[0]), "+f"(d[1]), "+f"(d[2]), "+f"(d[3])
                 : "r"(a[0]), "r"(a[1]), "r"(a[2]), "r"(a[3]), "r"(b[0]), "r"(b[1]));
}

__device__ __forceinline__ void split16(float v, __half &hi, __half &lo) {
    hi = __float2half_rn(v);
    lo = __float2half_rn(v - __half2float(hi));
}

// ================= init kernels =================
__global__ void init_state(const float* __restrict__ dh, const float* __restrict__ dc) {
    int idx = blockIdx.x * blockDim.x + threadIdx.x;   // 65536
    int l = idx >> 14, b = (idx >> 9) & 31, j = idx & 511;
    float h = dh[(l * 32 + b) * 512 + j];
    __half hi, lo; split16(h, hi, lo);
    g_A[0][l][b][512 + j]  = hi;
    g_A[0][l][b][1536 + j] = lo;
    g_c[l][b][j] = dc[(l * 32 + b) * 512 + j];
}

__global__ void init_emb(const float* __restrict__ emb, const int* __restrict__ target) {
    int idx = blockIdx.x * blockDim.x + threadIdx.x;   // 51*32*512 = 835584
    if (idx >= NTT * NB * NH) return;
    int t = idx >> 14, rem = idx & 16383, b = rem >> 9, k = rem & 511;
    int tok = (t == 0) ? 0 : target[b * NTT + t - 1];
    __half hi, lo; split16(emb[tok * 512 + k], hi, lo);
    g_embA[t][b][k] = hi;
    g_embA[t][b][1024 + k] = lo;
}

// build reordered combined LSTM weight: row2 = bj*128 + gate*32 + r  <->  n = gate*512 + bj*32 + r
// col k<512 from Wih, k>=512 from Whh; hi at k, lo at k+1024
__global__ void conv_wcat(const float* __restrict__ Wih, const float* __restrict__ Whh) {
    int idx = blockIdx.x * blockDim.x + threadIdx.x;   // 4*2048*128 = 1048576
    int l = idx >> 18, rem = idx & 262143, n = rem >> 7, k0 = (rem & 127) * 8;
    const float* src = (k0 < 512) ? (Wih + ((size_t)l * 2048 + n) * 512 + k0)
                                  : (Whh + ((size_t)l * 2048 + n) * 512 + (k0 - 512));
    float4 a = ((const float4*)src)[0], b = ((const float4*)src)[1];
    float v[8] = {a.x, a.y, a.z, a.w, b.x, b.y, b.z, b.w};
    __align__(16) __half hi[8], lo[8];
    #pragma unroll
    for (int i = 0; i < 8; i++) split16(v[i], hi[i], lo[i]);
    int g = n >> 9, r2 = n & 511, bj = r2 >> 5, r = r2 & 31;
    int row2 = bj * 128 + g * 32 + r;
    *(uint4*)&g_Wcat[l][row2][k0]        = *(const uint4*)hi;
    *(uint4*)&g_Wcat[l][row2][k0 + 1024] = *(const uint4*)lo;
}

// round W_out to fp16 once (projection B operand)
__global__ void conv_w(const float* __restrict__ W) {
    int idx = blockIdx.x * blockDim.x + threadIdx.x;   // 32000*64
    if (idx >= NV * 64) return;
    size_t base = (size_t)idx * 8;
    float4 a = ((const float4*)(W + base))[0], b = ((const float4*)(W + base))[1];
    float v[8] = {a.x, a.y, a.z, a.w, b.x, b.y, b.z, b.w};
    __align__(16) __half h[8];
    #pragma unroll
    for (int i = 0; i < 8; i++) h[i] = __float2half_rn(v[i]);
    *(uint4*)&g_Ws[base] = *(const uint4*)h;
}

// ================= tensor-core wavefront LSTM stage =================
// Per stage: 16 blocks x 256 threads. Block bj owns units j in [32bj, 32bj+32)
// across all 4 gates (W_cat rows bj*128..+128).
// gates[32b, 128n] = A_virt[32, 3072] @ Wcat_virt[128, 3072]^T  (3-term hi/lo)
//   chunk c (of 48, BK=64): cA = c<16 ? c : c-16 ; cW = c<32 ? c : c-32
// Fused pointwise cell update epilogue.
__global__ __launch_bounds__(256) void lstm_mma(
    int d, const float* __restrict__ bih, const float* __restrict__ bhh)
{
    extern __shared__ __align__(16) unsigned char ps[];
    const uint32_t sb = s2u(ps);
    const int tid = threadIdx.x, lane = tid & 31, wid = tid >> 5;
    const int wm = wid & 1, wn = wid >> 1;            // 2m x 4n warps
    const int lmin = (d > NTT - 1) ? d - (NTT - 1) : 0;
    const int bj = blockIdx.x & 15;
    const int l = lmin + (blockIdx.x >> 4);
    const int t = d - l;
    const int par = t & 1;

    const uint32_t Ab[2] = {sb, sb + 4096};           // 32x128B
    const uint32_t Bb[2] = {sb + 8192, sb + 24576};   // 128x128B

    const __half* Areg = &g_A[par][l][0][0];
    const __half* Aemb = &g_embA[t][0][0];
    const __half* Wb = &g_Wcat[l][0][0] + (size_t)(bj * 128) * 2048;

    float acc[4][4];
    #pragma unroll
    for (int p = 0; p < 4; p++)
        #pragma unroll
        for (int q = 0; q < 4; q++) acc[p][q] = 0.0f;

    auto load_chunk = [&](int c, int buf) {
        int cA = (c < 16) ? c : c - 16;
        int cW = (c < 32) ? c : c - 32;
        bool is_x = (cA < 8) || (cA >= 16 && cA < 24);
        const __half* As = (l == 0 && is_x) ? Aemb : Areg;
        {   // A tile 32 x 64 fp16: one 16B unit per thread
            int r = tid >> 3, u = tid & 7;
            cpasync16(Ab[buf] + r * 128 + ((u ^ (r & 7)) << 4),
                      As + (size_t)r * 2048 + cA * 64 + u * 8);
        }
        #pragma unroll
        for (int i = 0; i < 4; i++) {                 // B tile 128 x 64 fp16
            int s = tid + i * 256;
            int r = s >> 3, u = s & 7;
            cpasync16(Bb[buf] + r * 128 + ((u ^ (r & 7)) << 4),
                      Wb + (size_t)r * 2048 + cW * 64 + u * 8);
        }
    };

    load_chunk(0, 0);
    cp_commit();

    for (int c = 0; c < 48; c++) {
        if (c + 1 < 48) load_chunk(c + 1, (c + 1) & 1);
        cp_commit();
        cp_wait1();
        __syncthreads();

        const uint32_t Abase = Ab[c & 1], Bbase = Bb[c & 1];
        const int jA = lane >> 3;
        #pragma unroll
        for (int q = 0; q < 4; q++) {
            uint32_t a[4];
            {
                int r = wm * 16 + (lane & 7) + ((jA & 1) << 3);
                int uu = 2 * q + (jA >> 1);
                LDMX4(a[0], a[1], a[2], a[3], Abase + r * 128 + ((uu ^ (r & 7)) << 4));
            }
            uint32_t b[4][2];
            #pragma unroll
            for (int fp = 0; fp < 2; fp++) {
                int r = wn * 32 + fp * 16 + (lane & 7) + ((jA >> 1) << 3);
                int uu = 2 * q + (jA & 1);
                LDMX4(b[2 * fp][0], b[2 * fp][1], b[2 * fp + 1][0], b[2 * fp + 1][1],
                      Bbase + r * 128 + ((uu ^ (r & 7)) << 4));
            }
            #pragma unroll
            for (int p = 0; p < 4; p++) mma16816(acc[p], a, b[p]);
        }
        __syncthreads();
    }

    // ---- dump gates to smem (reuse pipeline smem), then fused cell update ----
    float* gatesS = (float*)ps;                       // [32][132] fp32 = 16.9KB
    __syncthreads();
    {
        int row0 = wm * 16 + (lane >> 2);
        #pragma unroll
        for (int p = 0; p < 4; p++) {
            int col = wn * 32 + p * 8 + 2 * (lane & 3);
            gatesS[row0 * 132 + col]           = acc[p][0];
            gatesS[row0 * 132 + col + 1]       = acc[p][1];
            gatesS[(row0 + 8) * 132 + col]     = acc[p][2];
            gatesS[(row0 + 8) * 132 + col + 1] = acc[p][3];
        }
    }
    __syncthreads();

    #pragma unroll
    for (int i = 0; i < 4; i++) {
        int idx = tid + i * 256;                      // 0..1023
        int jl = idx & 31, b = idx >> 5;
        int j = bj * 32 + jl;
        float gv[4];
        #pragma unroll
        for (int g = 0; g < 4; g++)
            gv[g] = gatesS[b * 132 + g * 32 + jl]
                  + bih[l * 2048 + g * 512 + j] + bhh[l * 2048 + g * 512 + j];
        float c0 = g_c[l][b][j];
        float iv = sigmoidf_(gv[0]), fv = sigmoidf_(gv[1]);
        float gg = tanhf(gv[2]),    ov = sigmoidf_(gv[3]);
        float cn = fv * c0 + iv * gg;
        float h  = ov * tanhf(cn);
        float hc = clip50(h);

        __half hhi, hlo; split16(hc, hhi, hlo);       // clamped -> recurrent h
        g_A[par ^ 1][l][b][512 + j]  = hhi;
        g_A[par ^ 1][l][b][1536 + j] = hlo;
        if (l < 3) {                                  // unclamped -> next layer x
            __half xhi, xlo; split16(h, xhi, xlo);
            g_A[par][l + 1][b][j]        = xhi;
            g_A[par][l + 1][b][1024 + j] = xlo;
        } else {                                      // unclamped -> projection
            g_Hs[((size_t)t * 32 + b) * 512 + j] = __float2half_rn(h);
        }
        g_c[l][b][j] = clip50(cn);
        if (t == NTT - 1) g_hfin[l][b][j] = hc;
    }
}

// ================= mma.sync fp16 projection (single pass, chunked M) =================
__global__ __launch_bounds__(256) void proj_mma(
    int mt, const float* __restrict__ bout, float* __restrict__ out)
{
    extern __shared__ __align__(16) unsigned char ps[];
    const uint32_t sb = s2u(ps);
    const int tid = threadIdx.x, lane = tid & 31, wid = tid >> 5;
    const int wm = wid & 3, wn = wid >> 2;
    const int bm = mt * 128, bn = blockIdx.x * 128;

    const uint32_t Ab[2] = {sb, sb + 16384};
    const uint32_t Bb[2] = {sb + 32768, sb + 49152};

    float acc[2][8][4];
    #pragma unroll
    for (int f = 0; f < 2; f++)
        #pragma unroll
        for (int p = 0; p < 8; p++)
            #pragma unroll
            for (int q = 0; q < 4; q++) acc[f][p][q] = 0.0f;

    const int sr = tid >> 3, su = tid & 7;

    #pragma unroll
    for (int i = 0; i < 4; i++) {
        int r = sr + i * 32;
        cpasync16(Ab[0] + r * 128 + ((su ^ (r & 7)) << 4),
                  g_Hs + (size_t)(bm + r) * 512 + su * 8);
        cpasync16(Bb[0] + r * 128 + ((su ^ (r & 7)) << 4),
                  g_Ws + (size_t)(bn + r) * 512 + su * 8);
    }
    cp_commit();

    for (int c = 0; c < 8; c++) {
        if (c + 1 < 8) {
            int k0 = (c + 1) * 64;
            uint32_t da = Ab[(c + 1) & 1], db = Bb[(c + 1) & 1];
            #pragma unroll
            for (int i = 0; i < 4; i++) {
                int r = sr + i * 32;
                cpasync16(da + r * 128 + ((su ^ (r & 7)) << 4),
                          g_Hs + (size_t)(bm + r) * 512 + k0 + su * 8);
                cpasync16(db + r * 128 + ((su ^ (r & 7)) << 4),
                          g_Ws + (size_t)(bn + r) * 512 + k0 + su * 8);
            }
        }
        cp_commit();
        cp_wait1();
        __syncthreads();

        const uint32_t Abase = Ab[c & 1], Bbase = Bb[c & 1];
        const int jA = lane >> 3;
        #pragma unroll
        for (int q = 0; q < 4; q++) {
            uint32_t a[2][4];
            #pragma unroll
            for (int f = 0; f < 2; f++) {
                int r = wm * 32 + f * 16 + (lane & 7) + ((jA & 1) << 3);
                int uu = 2 * q + (jA >> 1);
                LDMX4(a[f][0], a[f][1], a[f][2], a[f][3],
                      Abase + r * 128 + ((uu ^ (r & 7)) << 4));
            }
            uint32_t b[8][2];
            #pragma unroll
            for (int fp = 0; fp < 4; fp++) {
                int r = wn * 64 + fp * 16 + (lane & 7) + ((jA >> 1) << 3);
                int uu = 2 * q + (jA & 1);
                LDMX4(b[2 * fp][0], b[2 * fp][1], b[2 * fp + 1][0], b[2 * fp + 1][1],
                      Bbase + r * 128 + ((uu ^ (r & 7)) << 4));
            }
            #pragma unroll
            for (int f = 0; f < 2; f++)
                #pragma unroll
                for (int p = 0; p < 8; p++)
                    mma16816(acc[f][p], a[f], b[p]);
        }
        __syncthreads();
    }

    #pragma unroll
    for (int f = 0; f < 2; f++) {
        int m0 = bm + wm * 32 + f * 16 + (lane >> 2);
        #pragma unroll
        for (int p = 0; p < 8; p++) {
            int n = bn + wn * 64 + p * 8 + 2 * (lane & 3);
            float2 bo = *(const float2*)&bout[n];
            int m = m0;
            if (m < 1632) {
                int tt = m >> 5, b = m & 31;
                float2 r0 = make_float2(acc[f][p][0] + bo.x, acc[f][p][1] + bo.y);
                *(float2*)&out[(size_t)b * NTT * NV + (size_t)tt * NV + n] = r0;
            }
            m = m0 + 8;
            if (m < 1632) {
                int tt = m >> 5, b = m & 31;
                float2 r1 = make_float2(acc[f][p][2] + bo.x, acc[f][p][3] + bo.y);
                *(float2*)&out[(size_t)b * NTT * NV + (size_t)tt * NV + n] = r1;
            }
        }
    }
}

// ================= final hidden state tail =================
__global__ void write_hfin(float* __restrict__ out) {
    int idx = blockIdx.x * blockDim.x + threadIdx.x;   // 65536
    out[(size_t)NB * NTT * NV + idx] = (&g_hfin[0][0][0])[idx];
}

// ================= launcher: priority-asymmetric fork/join =================
extern "C" void kernel_launch(void* const* d_in, const int* in_sizes, int n_in,
                              void* d_out, int out_size)
{
    (void)in_sizes; (void)n_in; (void)out_size;
    const float* dh   = (const float*)d_in[1];
    const float* dc   = (const float*)d_in[2];
    const int*   tgt  = (const int*)  d_in[3];
    const float* emb  = (const float*)d_in[4];
    const float* Wih  = (const float*)d_in[5];
    const float* Whh  = (const float*)d_in[6];
    const float* bih  = (const float*)d_in[7];
    const float* bhh  = (const float*)d_in[8];
    const float* Wout = (const float*)d_in[9];
    const float* bout = (const float*)d_in[10];
    float* out = (float*)d_out;

    const int SMEM_PROJ = 65536;
    const int SMEM_LSTM = 40960;
    cudaFuncSetAttribute(proj_mma, cudaFuncAttributeMaxDynamicSharedMemorySize, SMEM_PROJ);
    cudaFuncSetAttribute(lstm_mma, cudaFuncAttributeMaxDynamicSharedMemorySize, SMEM_LSTM);

    // one-time resource creation (streams/events only; same work every call)
    static cudaStream_t s_hi = nullptr, s_lo = nullptr;
    static cudaEvent_t ev_start = nullptr, ev_hi_done = nullptr, ev_lo_done = nullptr, evF[13];
    static bool have_streams = false, tried = false;
    if (!tried) {
        tried = true;
        int prLeast = 0, prGreatest = 0;
        bool ok = (cudaDeviceGetStreamPriorityRange(&prLeast, &prGreatest) == cudaSuccess);
        ok = ok && (cudaStreamCreateWithPriority(&s_hi, cudaStreamNonBlocking, prGreatest) == cudaSuccess);
        ok = ok && (cudaStreamCreateWithPriority(&s_lo, cudaStreamNonBlocking, prLeast) == cudaSuccess);
        ok = ok && (cudaEventCreateWithFlags(&ev_start, cudaEventDisableTiming) == cudaSuccess);
        ok = ok && (cudaEventCreateWithFlags(&ev_hi_done, cudaEventDisableTiming) == cudaSuccess);
        ok = ok && (cudaEventCreateWithFlags(&ev_lo_done, cudaEventDisableTiming) == cudaSuccess);
        for (int i = 0; i < 13 && ok; i++)
            ok = (cudaEventCreateWithFlags(&evF[i], cudaEventDisableTiming) == cudaSuccess);
        have_streams = ok;
    }

    if (have_streams) {
        init_state<<<256, 256>>>(dh, dc);
        init_emb<<<3264, 256>>>(emb, tgt);
        cudaEventRecord(ev_start, 0);
        cudaStreamWaitEvent(s_hi, ev_start, 0);
        cudaStreamWaitEvent(s_lo, ev_start, 0);

        // HIGH priority: W_cat conversion then the LSTM critical path
        conv_wcat<<<4096, 256, 0, s_hi>>>(Wih, Whh);
        for (int d = 0; d < NDIAG; d++) {
            int lmin = (d > NTT - 1) ? d - (NTT - 1) : 0;
            int lmax = (d < NL - 1) ? d : NL - 1;
            int ns = lmax - lmin + 1;
            lstm_mma<<<16 * ns, 256, SMEM_LSTM, s_hi>>>(d, bih, bhh);
            if (d >= 6 && d <= 50 && ((d - 6) & 3) == 0)
                cudaEventRecord(evF[(d - 6) >> 2], s_hi);   // tiles 0..11 ready
        }
        cudaEventRecord(evF[12], s_hi);                      // tile 12: after d=53
        write_hfin<<<256, 256, 0, s_hi>>>(out);
        cudaEventRecord(ev_hi_done, s_hi);

        // LOW priority: proj W conversion then projection M-tiles (backfill)
        conv_w<<<8000, 256, 0, s_lo>>>(Wout);
        for (int i = 0; i < 13; i++) {
            cudaStreamWaitEvent(s_lo, evF[i], 0);
            proj_mma<<<dim3(250, 1), 256, SMEM_PROJ, s_lo>>>(i, bout, out);
        }
        cudaEventRecord(ev_lo_done, s_lo);

        cudaStreamWaitEvent((cudaStream_t)0, ev_hi_done, 0);
        cudaStreamWaitEvent((cudaStream_t)0, ev_lo_done, 0);
    } else {
        // fallback: fully serial
        init_state<<<256, 256>>>(dh, dc);
        init_emb<<<3264, 256>>>(emb, tgt);
        conv_wcat<<<4096, 256>>>(Wih, Whh);
        conv_w<<<8000, 256>>>(Wout);
        for (int d = 0; d < NDIAG; d++) {
            int lmin = (d > NTT - 1) ? d - (NTT - 1) : 0;
            int lmax = (d < NL - 1) ? d : NL - 1;
            int ns = lmax - lmin + 1;
            lstm_mma<<<16 * ns, 256, SMEM_LSTM>>>(d, bih, bhh);
        }
        for (int i = 0; i < 13; i++)
            proj_mma<<<dim3(250, 1), 256, SMEM_PROJ>>>(i, bout, out);
        write_hfin<<<256, 256>>>(out);
    }
}

// round 17
// speedup vs baseline: 1.3610x; 1.2888x over previous
#include <cuda_runtime.h>
#include <cuda_fp16.h>
#include <math.h>
#include <stdint.h>

#define NL 4
#define NB 32
#define NH 512
#define NV 32000
#define NTT 51
#define NDIAG (NTT + NL - 1)

// ================= persistent device scratch =================
// Activation buffers, fp16: k 0..511 = x_hi, 512..1023 = h_hi,
//                           1024..1535 = x_lo, 1536..2047 = h_lo
__device__ __half g_A[2][NL][NB][2048];      // ping-pong by t parity
__device__ __half g_embA[NTT][NB][2048];     // x-cols only, per timestep (l=0)
__device__ __half g_Wcat[NL][2048][2048];    // reordered combined W: hi(0:1024)|lo(1024:2048)
__device__ float  g_c[NL][NB][NH];           // cell state fp32 (clamped)
__device__ float  g_hfin[NL][NB][NH];        // final clamped hidden (t=50)
__device__ __half g_Hs[1664 * 512];          // proj A operand (pad rows stay 0)
__device__ __half g_Ws[NV * 512];            // proj B operand

// ================= helpers =================
__device__ __forceinline__ float sigmoidf_(float x) { return 1.0f / (1.0f + expf(-x)); }
__device__ __forceinline__ float clip50(float x) { return fminf(fmaxf(x, -50.0f), 50.0f); }

__device__ __forceinline__ uint32_t s2u(const void* p) {
    return (uint32_t)__cvta_generic_to_shared(p);
}
__device__ __forceinline__ void cpasync16(uint32_t dst, const void* src) {
    asm volatile("cp.async.cg.shared.global [%0], [%1], 16;" :: "r"(dst), "l"(src));
}
__device__ __forceinline__ void cp_commit() { asm volatile("cp.async.commit_group;" ::: "memory"); }
__device__ __forceinline__ void cp_wait1() { asm volatile("cp.async.wait_group 1;" ::: "memory"); }
__device__ __forceinline__ void cp_wait2() { asm volatile("cp.async.wait_group 2;" ::: "memory"); }

#define LDMX4(r0, r1, r2, r3, a) \
    asm volatile("ldmatrix.sync.aligned.m8n8.x4.shared.b16 {%0,%1,%2,%3}, [%4];" \
                 : "=r"(r0), "=r"(r1), "=r"(r2), "=r"(r3) : "r"(a))

__device__ __forceinline__ void mma16816(float* d, const uint32_t* a, const uint32_t* b) {
    asm volatile("mma.sync.aligned.m16n8k16.row.col.f32.f16.f16.f32 "
                 "{%0,%1,%2,%3}, {%4,%5,%6,%7}, {%8,%9}, {%0,%1,%2,%3};"
                 : "+f"(d[0]), "+f"(d[1]), "+f"(d[2]), "+f"(d[3])
                 : "r"(a[0]), "r"(a[1]), "r"(a[2]), "r"(a[3]), "r"(b[0]), "r"(b[1]));
}

__device__ __forceinline__ void split16(float v, __half &hi, __half &lo) {
    hi = __float2half_rn(v);
    lo = __float2half_rn(v - __half2float(hi));
}

// ================= init kernels =================
__global__ void init_state(const float* __restrict__ dh, const float* __restrict__ dc) {
    int idx = blockIdx.x * blockDim.x + threadIdx.x;   // 65536
    int l = idx >> 14, b = (idx >> 9) & 31, j = idx & 511;
    float h = dh[(l * 32 + b) * 512 + j];
    __half hi, lo; split16(h, hi, lo);
    g_A[0][l][b][512 + j]  = hi;
    g_A[0][l][b][1536 + j] = lo;
    g_c[l][b][j] = dc[(l * 32 + b) * 512 + j];
}

__global__ void init_emb(const float* __restrict__ emb, const int* __restrict__ target) {
    int idx = blockIdx.x * blockDim.x + threadIdx.x;   // 51*32*512 = 835584
    if (idx >= NTT * NB * NH) return;
    int t = idx >> 14, rem = idx & 16383, b = rem >> 9, k = rem & 511;
    int tok = (t == 0) ? 0 : target[b * NTT + t - 1];
    __half hi, lo; split16(emb[tok * 512 + k], hi, lo);
    g_embA[t][b][k] = hi;
    g_embA[t][b][1024 + k] = lo;
}

// build reordered combined LSTM weight:
//   n = gate*512 + j  ->  row2 = (j>>4)*64 + gate*16 + (j&15)   (32 blocks x 64 rows)
// col k<512 from Wih, k>=512 from Whh; hi at k, lo at k+1024
__global__ void conv_wcat(const float* __restrict__ Wih, const float* __restrict__ Whh) {
    int idx = blockIdx.x * blockDim.x + threadIdx.x;   // 4*2048*128 = 1048576
    int l = idx >> 18, rem = idx & 262143, n = rem >> 7, k0 = (rem & 127) * 8;
    const float* src = (k0 < 512) ? (Wih + ((size_t)l * 2048 + n) * 512 + k0)
                                  : (Whh + ((size_t)l * 2048 + n) * 512 + (k0 - 512));
    float4 a = ((const float4*)src)[0], b = ((const float4*)src)[1];
    float v[8] = {a.x, a.y, a.z, a.w, b.x, b.y, b.z, b.w};
    __align__(16) __half hi[8], lo[8];
    #pragma unroll
    for (int i = 0; i < 8; i++) split16(v[i], hi[i], lo[i]);
    int g = n >> 9, j = n & 511;
    int row2 = (j >> 4) * 64 + g * 16 + (j & 15);
    *(uint4*)&g_Wcat[l][row2][k0]        = *(const uint4*)hi;
    *(uint4*)&g_Wcat[l][row2][k0 + 1024] = *(const uint4*)lo;
}

// round W_out to fp16 once (projection B operand)
__global__ void conv_w(const float* __restrict__ W) {
    int idx = blockIdx.x * blockDim.x + threadIdx.x;   // 32000*64
    if (idx >= NV * 64) return;
    size_t base = (size_t)idx * 8;
    float4 a = ((const float4*)(W + base))[0], b = ((const float4*)(W + base))[1];
    float v[8] = {a.x, a.y, a.z, a.w, b.x, b.y, b.z, b.w};
    __align__(16) __half h[8];
    #pragma unroll
    for (int i = 0; i < 8; i++) h[i] = __float2half_rn(v[i]);
    *(uint4*)&g_Ws[base] = *(const uint4*)h;
}

// ================= tensor-core wavefront LSTM stage (v2) =================
// Per stage: 32 blocks x 256 threads. Block bk owns units j in [16bk, 16bk+16)
// across all 4 gates (W_cat rows bk*64..+64).
// gates[32b, 64n] = A_virt[32, 3072] @ Wcat_virt[64, 3072]^T  (3-term hi/lo)
// 48 chunks of BK=64, depth-3 cp.async pipeline. Fused cell-update epilogue.
__global__ __launch_bounds__(256) void lstm_mma(
    int d, const float* __restrict__ bih, const float* __restrict__ bhh)
{
    extern __shared__ __align__(16) unsigned char ps[];
    const uint32_t sb = s2u(ps);
    const int tid = threadIdx.x, lane = tid & 31, wid = tid >> 5;
    const int wm = wid & 1, wn = wid >> 1;            // 2m x 4n warps, warp tile 16x16
    const int lmin = (d > NTT - 1) ? d - (NTT - 1) : 0;
    const int bk = blockIdx.x & 31;
    const int l = lmin + (blockIdx.x >> 5);
    const int t = d - l;
    const int par = t & 1;

    const uint32_t Ab[3] = {sb, sb + 4096, sb + 8192};            // 32x128B each
    const uint32_t Bb[3] = {sb + 12288, sb + 20480, sb + 28672};  // 64x128B each

    const __half* Areg = &g_A[par][l][0][0];
    const __half* Aemb = &g_embA[t][0][0];
    const __half* Wb = &g_Wcat[l][0][0] + (size_t)(bk * 64) * 2048;

    float acc[2][4];
    #pragma unroll
    for (int p = 0; p < 2; p++)
        #pragma unroll
        for (int q = 0; q < 4; q++) acc[p][q] = 0.0f;

    auto load_chunk = [&](int c, int buf) {
        int cA = (c < 16) ? c : c - 16;
        int cW = (c < 32) ? c : c - 32;
        bool is_x = (cA < 8) || (cA >= 16 && cA < 24);
        const __half* As = (l == 0 && is_x) ? Aemb : Areg;
        {   // A tile 32 x 64 fp16: one 16B unit per thread
            int r = tid >> 3, u = tid & 7;
            cpasync16(Ab[buf] + r * 128 + ((u ^ (r & 7)) << 4),
                      As + (size_t)r * 2048 + cA * 64 + u * 8);
        }
        #pragma unroll
        for (int i = 0; i < 2; i++) {                 // B tile 64 x 64 fp16
            int s = tid + i * 256;
            int r = s >> 3, u = s & 7;
            cpasync16(Bb[buf] + r * 128 + ((u ^ (r & 7)) << 4),
                      Wb + (size_t)r * 2048 + cW * 64 + u * 8);
        }
    };

    load_chunk(0, 0); cp_commit();
    load_chunk(1, 1); cp_commit();

    int buf = 0;
    for (int c = 0; c < 48; c++) {
        if (c + 2 < 48) {
            int nb = buf + 2; if (nb >= 3) nb -= 3;
            load_chunk(c + 2, nb);
        }
        cp_commit();            // empty group near the tail keeps accounting uniform
        cp_wait2();             // chunk c (commit #c+1 of #c+3) is complete
        __syncthreads();

        const uint32_t Abase = Ab[buf], Bbase = Bb[buf];
        const int jA = lane >> 3;
        #pragma unroll
        for (int q = 0; q < 4; q++) {
            uint32_t a[4];
            {
                int r = wm * 16 + (lane & 7) + ((jA & 1) << 3);
                int uu = 2 * q + (jA >> 1);
                LDMX4(a[0], a[1], a[2], a[3], Abase + r * 128 + ((uu ^ (r & 7)) << 4));
            }
            uint32_t b[2][2];
            {
                int r = wn * 16 + (lane & 7) + ((jA >> 1) << 3);
                int uu = 2 * q + (jA & 1);
                LDMX4(b[0][0], b[0][1], b[1][0], b[1][1],
                      Bbase + r * 128 + ((uu ^ (r & 7)) << 4));
            }
            mma16816(acc[0], a, b[0]);
            mma16816(acc[1], a, b[1]);
        }
        __syncthreads();
        if (++buf == 3) buf = 0;
    }

    // ---- dump gates to smem (reuse pipeline smem), then fused cell update ----
    float* gatesS = (float*)ps;                       // [32][68] fp32 = 8.7KB
    __syncthreads();
    {
        int row0 = wm * 16 + (lane >> 2);
        #pragma unroll
        for (int p = 0; p < 2; p++) {
            int col = wn * 16 + p * 8 + 2 * (lane & 3);
            gatesS[row0 * 68 + col]           = acc[p][0];
            gatesS[row0 * 68 + col + 1]       = acc[p][1];
            gatesS[(row0 + 8) * 68 + col]     = acc[p][2];
            gatesS[(row0 + 8) * 68 + col + 1] = acc[p][3];
        }
    }
    __syncthreads();

    #pragma unroll
    for (int i = 0; i < 2; i++) {
        int idx = tid + i * 256;                      // 0..511
        int rr = idx & 15, b = idx >> 4;
        int j = bk * 16 + rr;
        float gv[4];
        #pragma unroll
        for (int g = 0; g < 4; g++)
            gv[g] = gatesS[b * 68 + g * 16 + rr]
                  + bih[l * 2048 + g * 512 + j] + bhh[l * 2048 + g * 512 + j];
        float c0 = g_c[l][b][j];
        float iv = sigmoidf_(gv[0]), fv = sigmoidf_(gv[1]);
        float gg = tanhf(gv[2]),    ov = sigmoidf_(gv[3]);
        float cn = fv * c0 + iv * gg;
        float h  = ov * tanhf(cn);
        float hc = clip50(h);

        __half hhi, hlo; split16(hc, hhi, hlo);       // clamped -> recurrent h
        g_A[par ^ 1][l][b][512 + j]  = hhi;
        g_A[par ^ 1][l][b][1536 + j] = hlo;
        if (l < 3) {                                  // unclamped -> next layer x
            __half xhi, xlo; split16(h, xhi, xlo);
            g_A[par][l + 1][b][j]        = xhi;
            g_A[par][l + 1][b][1024 + j] = xlo;
        } else {                                      // unclamped -> projection
            g_Hs[((size_t)t * 32 + b) * 512 + j] = __float2half_rn(h);
        }
        g_c[l][b][j] = clip50(cn);
        if (t == NTT - 1) g_hfin[l][b][j] = hc;
    }
}

// ================= mma.sync fp16 projection (single pass, chunked M) =================
__global__ __launch_bounds__(256) void proj_mma(
    int mt, const float* __restrict__ bout, float* __restrict__ out)
{
    extern __shared__ __align__(16) unsigned char ps[];
    const uint32_t sb = s2u(ps);
    const int tid = threadIdx.x, lane = tid & 31, wid = tid >> 5;
    const int wm = wid & 3, wn = wid >> 2;
    const int bm = mt * 128, bn = blockIdx.x * 128;

    const uint32_t Ab[2] = {sb, sb + 16384};
    const uint32_t Bb[2] = {sb + 32768, sb + 49152};

    float acc[2][8][4];
    #pragma unroll
    for (int f = 0; f < 2; f++)
        #pragma unroll
        for (int p = 0; p < 8; p++)
            #pragma unroll
            for (int q = 0; q < 4; q++) acc[f][p][q] = 0.0f;

    const int sr = tid >> 3, su = tid & 7;

    #pragma unroll
    for (int i = 0; i < 4; i++) {
        int r = sr + i * 32;
        cpasync16(Ab[0] + r * 128 + ((su ^ (r & 7)) << 4),
                  g_Hs + (size_t)(bm + r) * 512 + su * 8);
        cpasync16(Bb[0] + r * 128 + ((su ^ (r & 7)) << 4),
                  g_Ws + (size_t)(bn + r) * 512 + su * 8);
    }
    cp_commit();

    for (int c = 0; c < 8; c++) {
        if (c + 1 < 8) {
            int k0 = (c + 1) * 64;
            uint32_t da = Ab[(c + 1) & 1], db = Bb[(c + 1) & 1];
            #pragma unroll
            for (int i = 0; i < 4; i++) {
                int r = sr + i * 32;
                cpasync16(da + r * 128 + ((su ^ (r & 7)) << 4),
                          g_Hs + (size_t)(bm + r) * 512 + k0 + su * 8);
                cpasync16(db + r * 128 + ((su ^ (r & 7)) << 4),
                          g_Ws + (size_t)(bn + r) * 512 + k0 + su * 8);
            }
        }
        cp_commit();
        cp_wait1();
        __syncthreads();

        const uint32_t Abase = Ab[c & 1], Bbase = Bb[c & 1];
        const int jA = lane >> 3;
        #pragma unroll
        for (int q = 0; q < 4; q++) {
            uint32_t a[2][4];
            #pragma unroll
            for (int f = 0; f < 2; f++) {
                int r = wm * 32 + f * 16 + (lane & 7) + ((jA & 1) << 3);
                int uu = 2 * q + (jA >> 1);
                LDMX4(a[f][0], a[f][1], a[f][2], a[f][3],
                      Abase + r * 128 + ((uu ^ (r & 7)) << 4));
            }
            uint32_t b[8][2];
            #pragma unroll
            for (int fp = 0; fp < 4; fp++) {
                int r = wn * 64 + fp * 16 + (lane & 7) + ((jA >> 1) << 3);
                int uu = 2 * q + (jA & 1);
                LDMX4(b[2 * fp][0], b[2 * fp][1], b[2 * fp + 1][0], b[2 * fp + 1][1],
                      Bbase + r * 128 + ((uu ^ (r & 7)) << 4));
            }
            #pragma unroll
            for (int f = 0; f < 2; f++)
                #pragma unroll
                for (int p = 0; p < 8; p++)
                    mma16816(acc[f][p], a[f], b[p]);
        }
        __syncthreads();
    }

    #pragma unroll
    for (int f = 0; f < 2; f++) {
        int m0 = bm + wm * 32 + f * 16 + (lane >> 2);
        #pragma unroll
        for (int p = 0; p < 8; p++) {
            int n = bn + wn * 64 + p * 8 + 2 * (lane & 3);
            float2 bo = *(const float2*)&bout[n];
            int m = m0;
            if (m < 1632) {
                int tt = m >> 5, b = m & 31;
                float2 r0 = make_float2(acc[f][p][0] + bo.x, acc[f][p][1] + bo.y);
                *(float2*)&out[(size_t)b * NTT * NV + (size_t)tt * NV + n] = r0;
            }
            m = m0 + 8;
            if (m < 1632) {
                int tt = m >> 5, b = m & 31;
                float2 r1 = make_float2(acc[f][p][2] + bo.x, acc[f][p][3] + bo.y);
                *(float2*)&out[(size_t)b * NTT * NV + (size_t)tt * NV + n] = r1;
            }
        }
    }
}

// ================= final hidden state tail =================
__global__ void write_hfin(float* __restrict__ out) {
    int idx = blockIdx.x * blockDim.x + threadIdx.x;   // 65536
    out[(size_t)NB * NTT * NV + idx] = (&g_hfin[0][0][0])[idx];
}

// ================= launcher: priority-asymmetric fork/join =================
extern "C" void kernel_launch(void* const* d_in, const int* in_sizes, int n_in,
                              void* d_out, int out_size)
{
    (void)in_sizes; (void)n_in; (void)out_size;
    const float* dh   = (const float*)d_in[1];
    const float* dc   = (const float*)d_in[2];
    const int*   tgt  = (const int*)  d_in[3];
    const float* emb  = (const float*)d_in[4];
    const float* Wih  = (const float*)d_in[5];
    const float* Whh  = (const float*)d_in[6];
    const float* bih  = (const float*)d_in[7];
    const float* bhh  = (const float*)d_in[8];
    const float* Wout = (const float*)d_in[9];
    const float* bout = (const float*)d_in[10];
    float* out = (float*)d_out;

    const int SMEM_PROJ = 65536;
    const int SMEM_LSTM = 36864;
    cudaFuncSetAttribute(proj_mma, cudaFuncAttributeMaxDynamicSharedMemorySize, SMEM_PROJ);
    cudaFuncSetAttribute(lstm_mma, cudaFuncAttributeMaxDynamicSharedMemorySize, SMEM_LSTM);

    // one-time resource creation (streams/events only; same work every call)
    static cudaStream_t s_hi = nullptr, s_lo = nullptr;
    static cudaEvent_t ev_start = nullptr, ev_hi_done = nullptr, ev_lo_done = nullptr, evF[13];
    static bool have_streams = false, tried = false;
    if (!tried) {
        tried = true;
        int prLeast = 0, prGreatest = 0;
        bool ok = (cudaDeviceGetStreamPriorityRange(&prLeast, &prGreatest) == cudaSuccess);
        ok = ok && (cudaStreamCreateWithPriority(&s_hi, cudaStreamNonBlocking, prGreatest) == cudaSuccess);
        ok = ok && (cudaStreamCreateWithPriority(&s_lo, cudaStreamNonBlocking, prLeast) == cudaSuccess);
        ok = ok && (cudaEventCreateWithFlags(&ev_start, cudaEventDisableTiming) == cudaSuccess);
        ok = ok && (cudaEventCreateWithFlags(&ev_hi_done, cudaEventDisableTiming) == cudaSuccess);
        ok = ok && (cudaEventCreateWithFlags(&ev_lo_done, cudaEventDisableTiming) == cudaSuccess);
        for (int i = 0; i < 13 && ok; i++)
            ok = (cudaEventCreateWithFlags(&evF[i], cudaEventDisableTiming) == cudaSuccess);
        have_streams = ok;
    }

    if (have_streams) {
        init_state<<<256, 256>>>(dh, dc);
        init_emb<<<3264, 256>>>(emb, tgt);
        cudaEventRecord(ev_start, 0);
        cudaStreamWaitEvent(s_hi, ev_start, 0);
        cudaStreamWaitEvent(s_lo, ev_start, 0);

        // HIGH priority: W_cat conversion then the LSTM critical path
        conv_wcat<<<4096, 256, 0, s_hi>>>(Wih, Whh);
        for (int d = 0; d < NDIAG; d++) {
            int lmin = (d > NTT - 1) ? d - (NTT - 1) : 0;
            int lmax = (d < NL - 1) ? d : NL - 1;
            int ns = lmax - lmin + 1;
            lstm_mma<<<32 * ns, 256, SMEM_LSTM, s_hi>>>(d, bih, bhh);
            if (d >= 6 && d <= 50 && ((d - 6) & 3) == 0)
                cudaEventRecord(evF[(d - 6) >> 2], s_hi);   // tiles 0..11 ready
        }
        cudaEventRecord(evF[12], s_hi);                      // tile 12: after d=53
        write_hfin<<<256, 256, 0, s_hi>>>(out);
        cudaEventRecord(ev_hi_done, s_hi);

        // LOW priority: proj W conversion then projection M-tiles (backfill)
        conv_w<<<8000, 256, 0, s_lo>>>(Wout);
        for (int i = 0; i < 13; i++) {
            cudaStreamWaitEvent(s_lo, evF[i], 0);
            proj_mma<<<dim3(250, 1), 256, SMEM_PROJ, s_lo>>>(i, bout, out);
        }
        cudaEventRecord(ev_lo_done, s_lo);

        cudaStreamWaitEvent((cudaStream_t)0, ev_hi_done, 0);
        cudaStreamWaitEvent((cudaStream_t)0, ev_lo_done, 0);
    } else {
        // fallback: fully serial
        init_state<<<256, 256>>>(dh, dc);
        init_emb<<<3264, 256>>>(emb, tgt);
        conv_wcat<<<4096, 256>>>(Wih, Whh);
        conv_w<<<8000, 256>>>(Wout);
        for (int d = 0; d < NDIAG; d++) {
            int lmin = (d > NTT - 1) ? d - (NTT - 1) : 0;
            int lmax = (d < NL - 1) ? d : NL - 1;
            int ns = lmax - lmin + 1;
            lstm_mma<<<32 * ns, 256, SMEM_LSTM>>>(d, bih, bhh);
        }
        for (int i = 0; i < 13; i++)
            proj_mma<<<dim3(250, 1), 256, SMEM_PROJ>>>(i, bout, out);
        write_hfin<<<256, 256>>>(out);
    }
}